// round 1
// baseline (speedup 1.0000x reference)
#include <cuda_runtime.h>
#include <cstdint>

// Problem shape (fixed by the dataset)
#define BATCH   8
#define SEQ     4096
#define CHANS   1024

// Tiling
#define CHUNK_T 256                 // timesteps per block
#define CG      32                  // channels per block
#define NCHUNK  (SEQ / CHUNK_T)     // 16
#define CGRP    (CHANS / CG)        // 32
#define SUBS    8                   // warps per block; each warp owns 32 timesteps
#define TPW     (CHUNK_T / SUBS)    // 32 timesteps per thread

// Decoupled-lookback descriptors: one 64-bit word per (b, chunk, channel).
// upper 32 bits = flag (0 = invalid, 1 = aggregate, 2 = inclusive prefix)
// lower 32 bits = float payload bits.
#define NDESC (BATCH * NCHUNK * CHANS)
__device__ unsigned long long g_desc[NDESC];

__device__ __forceinline__ unsigned long long pack_desc(unsigned flag, float v) {
    return ((unsigned long long)flag << 32) | (unsigned long long)__float_as_uint(v);
}
__device__ __forceinline__ unsigned desc_flag(unsigned long long v) { return (unsigned)(v >> 32); }
__device__ __forceinline__ float    desc_val (unsigned long long v) { return __uint_as_float((unsigned)v); }

__global__ void init_desc_kernel() {
    int i = blockIdx.x * blockDim.x + threadIdx.x;
    if (i < NDESC) g_desc[i] = 0ULL;
}

__global__ __launch_bounds__(256, 4)
void scan_kernel(const float* __restrict__ x, const float* __restrict__ d,
                 float* __restrict__ y) {
    __shared__ float tile[CHUNK_T][CG];   // 32 KB; bank = lane -> conflict-free
    __shared__ float sub_b[SUBS][CG];     // per-warp local aggregates
    __shared__ float seed [SUBS][CG];     // per-warp starting y value

    const int cg   = blockIdx.x;          // channel group
    const int b    = blockIdx.y;          // batch
    const int k    = blockIdx.z;          // chunk index along t (slowest -> in-order ids)
    const int tid  = threadIdx.x;
    const int lane = tid & 31;            // channel within group
    const int sub  = tid >> 5;            // warp id == t-slab id

    const int c = cg * CG + lane;
    const float dc = d[c];
    // d^32 by repeated squaring
    const float d2 = dc * dc, d4 = d2 * d2, d8 = d4 * d4, d16 = d8 * d8, d32 = d16 * d16;

    const size_t base = ((size_t)b * SEQ + (size_t)k * CHUNK_T) * CHANS + (size_t)cg * CG;
    const float* xb = x + base;
    float*       yb = y + base;

    // ---- Load own 32-row slab + local reduce (loads independent of FFMA chain) ----
    float bloc = 0.0f;
    #pragma unroll
    for (int i = 0; i < TPW; i++) {
        float v = xb[(size_t)(sub * TPW + i) * CHANS + lane];
        tile[sub * TPW + i][lane] = v;
        bloc = dc * bloc + v;
    }
    sub_b[sub][lane] = bloc;
    __syncthreads();

    // ---- Warp 0: combine sub aggregates, publish, lookback, compute seeds ----
    if (tid < 32) {
        const float d64 = d32 * d32, d128 = d64 * d64, d256 = d128 * d128;

        // Sequential scan over the 8 sub-slabs for channel `lane`:
        // running B after sub s: B = d32*B + b_s.  Record exclusive prefixes in seed[].
        float B = 0.0f;
        #pragma unroll
        for (int s = 0; s < SUBS; s++) {
            seed[s][lane] = B;            // exclusive (before carry applied)
            B = d32 * B + sub_b[s][lane];
        }

        const int didx = (b * NCHUNK + k) * CHANS + c;
        float carry = 0.0f;

        if (k == 0) {
            // First chunk: inclusive == aggregate
            atomicExch(&g_desc[didx], pack_desc(2u, B));
        } else {
            atomicExch(&g_desc[didx], pack_desc(1u, B));   // publish aggregate early
            // Decoupled lookback: carry = sum_j d256^{k-1-j} * B_j
            float factor = 1.0f;
            int j = k - 1;
            for (;;) {
                unsigned long long v;
                do {
                    v = atomicAdd(&g_desc[(b * NCHUNK + j) * CHANS + c], 0ULL);
                } while (desc_flag(v) == 0u);
                if (desc_flag(v) == 2u) { carry += factor * desc_val(v); break; }
                carry += factor * desc_val(v);
                factor *= d256;
                j--;                       // chunk 0 always publishes flag 2 -> terminates
            }
            atomicExch(&g_desc[didx], pack_desc(2u, d256 * carry + B));
        }

        // seed[s] = d^{32 s} * carry + exclusive_prefix(s)
        float p = 1.0f;
        #pragma unroll
        for (int s = 0; s < SUBS; s++) {
            seed[s][lane] = p * carry + seed[s][lane];
            p *= d32;
        }
    }
    __syncthreads();

    // ---- Apply pass: seeded recurrence over own slab, coalesced stores ----
    float yv = seed[sub][lane];
    #pragma unroll
    for (int i = 0; i < TPW; i++) {
        yv = dc * yv + tile[sub * TPW + i][lane];
        yb[(size_t)(sub * TPW + i) * CHANS + lane] = yv;
    }
}

extern "C" void kernel_launch(void* const* d_in, const int* in_sizes, int n_in,
                              void* d_out, int out_size) {
    const float* x = (const float*)d_in[0];
    const float* d = (const float*)d_in[1];
    float* y = (float*)d_out;
    (void)in_sizes; (void)n_in; (void)out_size;

    init_desc_kernel<<<(NDESC + 255) / 256, 256>>>();

    dim3 grid(CGRP, BATCH, NCHUNK);   // chunk on z: predecessors have smaller linear ids
    scan_kernel<<<grid, 256>>>(x, d, y);
}

// round 2
// speedup vs baseline: 1.1176x; 1.1176x over previous
#include <cuda_runtime.h>
#include <cstdint>

// Problem shape (fixed by the dataset)
#define BATCH   8
#define SEQ     4096
#define CHANS   1024

// Tiling: block = 8 warps; each warp = 32 lanes x float4 = 128 channels, 8 rows
#define CG      128                  // channels per block
#define ROWS_W  8                    // timesteps per warp (per thread)
#define WARPS   8
#define CHUNK_T (ROWS_W * WARPS)     // 64 timesteps per block
#define NCHUNK  (SEQ / CHUNK_T)      // 64
#define CGRP    (CHANS / CG)         // 8
#define L4      (CG / 4)             // 32 float4 lanes per row

// Lookback state: one flag per (b, cgroup, chunk) + float4 value arrays.
// flag: 0 = invalid, 1 = aggregate valid, 2 = inclusive valid
#define NFLAG (BATCH * CGRP * NCHUNK)
__device__ int    g_flag[NFLAG];
__device__ float4 g_agg [NFLAG * L4];
__device__ float4 g_inc [NFLAG * L4];

__global__ void init_flags_kernel() {
    int i = blockIdx.x * blockDim.x + threadIdx.x;
    if (i < NFLAG) g_flag[i] = 0;
}

__device__ __forceinline__ float4 f4_fma(float4 a, float4 b, float4 c) {
    // a*b + c componentwise
    float4 r;
    r.x = fmaf(a.x, b.x, c.x); r.y = fmaf(a.y, b.y, c.y);
    r.z = fmaf(a.z, b.z, c.z); r.w = fmaf(a.w, b.w, c.w);
    return r;
}

__global__ __launch_bounds__(256, 4)
void scan_kernel(const float4* __restrict__ x, const float4* __restrict__ d,
                 float4* __restrict__ y) {
    __shared__ float4 sub_b[WARPS][L4];   // per-warp aggregates
    __shared__ float4 seed [WARPS][L4];   // per-warp starting y

    const int cg   = blockIdx.x;          // channel group
    const int b    = blockIdx.y;          // batch
    const int k    = blockIdx.z;          // chunk (slowest -> in-order block ids)
    const int tid  = threadIdx.x;
    const int lane = tid & 31;            // float4 column within group
    const int w    = tid >> 5;            // warp id == row-slab id

    const int col = cg * L4 + lane;       // global float4 column
    const float4 dv = d[col];

    const size_t rowstride = CHANS / 4;   // 256 float4 per row
    const size_t base = ((size_t)b * SEQ + (size_t)k * CHUNK_T + (size_t)w * ROWS_W) * rowstride + col;
    const float4* xb = x + base;
    float4*       yb = y + base;

    // ---- Load 8 rows into registers + local aggregate (loads independent) ----
    float4 xr[ROWS_W];
    float4 Bv = make_float4(0.f, 0.f, 0.f, 0.f);
    #pragma unroll
    for (int i = 0; i < ROWS_W; i++) {
        xr[i] = xb[(size_t)i * rowstride];
        Bv = f4_fma(dv, Bv, xr[i]);
    }
    sub_b[w][lane] = Bv;
    __syncthreads();

    // ---- Warp 0: combine warp aggregates, publish, lookback, seeds ----
    if (tid < 32) {
        // d^8 and d^64 per channel
        float4 d2 = f4_fma(dv, dv, make_float4(0,0,0,0));
        d2.x = dv.x*dv.x; d2.y = dv.y*dv.y; d2.z = dv.z*dv.z; d2.w = dv.w*dv.w;
        float4 d4, d8, d16, d32, d64;
        d4.x=d2.x*d2.x; d4.y=d2.y*d2.y; d4.z=d2.z*d2.z; d4.w=d2.w*d2.w;
        d8.x=d4.x*d4.x; d8.y=d4.y*d4.y; d8.z=d4.z*d4.z; d8.w=d4.w*d4.w;
        d16.x=d8.x*d8.x; d16.y=d8.y*d8.y; d16.z=d8.z*d8.z; d16.w=d8.w*d8.w;
        d32.x=d16.x*d16.x; d32.y=d16.y*d16.y; d32.z=d16.z*d16.z; d32.w=d16.w*d16.w;
        d64.x=d32.x*d32.x; d64.y=d32.y*d32.y; d64.z=d32.z*d32.z; d64.w=d32.w*d32.w;

        // Sequential combine across the 8 warp slabs (factor d^8)
        float4 B = make_float4(0.f, 0.f, 0.f, 0.f);
        #pragma unroll
        for (int s = 0; s < WARPS; s++) {
            seed[s][lane] = B;            // exclusive, pre-carry
            B = f4_fma(d8, B, sub_b[s][lane]);
        }

        const int fidx = (b * CGRP + cg) * NCHUNK + k;
        float4 carry = make_float4(0.f, 0.f, 0.f, 0.f);

        if (k == 0) {
            g_inc[fidx * L4 + lane] = B;
            __threadfence();
            if (lane == 0) atomicExch(&g_flag[fidx], 2);
        } else {
            // publish aggregate early
            g_agg[fidx * L4 + lane] = B;
            __threadfence();
            if (lane == 0) atomicExch(&g_flag[fidx], 1);

            // decoupled lookback: carry = sum_j d64^{k-1-j} * B_j, stop at inclusive
            float4 factor = make_float4(1.f, 1.f, 1.f, 1.f);
            int j = k - 1;
            for (;;) {
                int f;
                if (lane == 0) {
                    do { f = atomicAdd(&g_flag[(b * CGRP + cg) * NCHUNK + j], 0); } while (f == 0);
                }
                f = __shfl_sync(0xffffffffu, f, 0);
                __threadfence();
                const int vidx = ((b * CGRP + cg) * NCHUNK + j) * L4 + lane;
                if (f == 2) {
                    float4 v = __ldcg(&g_inc[vidx]);
                    carry = f4_fma(factor, v, carry);
                    break;
                }
                float4 v = __ldcg(&g_agg[vidx]);
                carry = f4_fma(factor, v, carry);
                factor.x *= d64.x; factor.y *= d64.y; factor.z *= d64.z; factor.w *= d64.w;
                j--;                      // chunk 0 always reaches flag 2 -> terminates
            }
            // publish inclusive
            float4 inc = f4_fma(d64, carry, B);
            g_inc[fidx * L4 + lane] = inc;
            __threadfence();
            if (lane == 0) atomicExch(&g_flag[fidx], 2);
        }

        // seed[s] = d^{8 s} * carry + exclusive_prefix(s)
        float4 p = make_float4(1.f, 1.f, 1.f, 1.f);
        #pragma unroll
        for (int s = 0; s < WARPS; s++) {
            float4 e = seed[s][lane];
            seed[s][lane] = f4_fma(p, carry, e);
            p.x *= d8.x; p.y *= d8.y; p.z *= d8.z; p.w *= d8.w;
        }
    }
    __syncthreads();

    // ---- Apply: seeded recurrence over register-resident rows, float4 stores ----
    float4 yv = seed[w][lane];
    #pragma unroll
    for (int i = 0; i < ROWS_W; i++) {
        yv = f4_fma(dv, yv, xr[i]);
        yb[(size_t)i * rowstride] = yv;
    }
}

extern "C" void kernel_launch(void* const* d_in, const int* in_sizes, int n_in,
                              void* d_out, int out_size) {
    const float4* x = (const float4*)d_in[0];
    const float4* d = (const float4*)d_in[1];
    float4* y = (float4*)d_out;
    (void)in_sizes; (void)n_in; (void)out_size;

    init_flags_kernel<<<(NFLAG + 255) / 256, 256>>>();

    dim3 grid(CGRP, BATCH, NCHUNK);   // chunk on z: predecessors have smaller linear ids
    scan_kernel<<<grid, 256>>>(x, d, y);
}